// round 3
// baseline (speedup 1.0000x reference)
#include <cuda_runtime.h>
#include <math.h>

#define NN 10000
#define NE 160000
#define EPW 4

// ---------------- scratch (static device globals; no allocation) ------------
__device__ float g_Y[NN * 160];     // y0|y1 per node (lin1 output), 6.4 MB
__device__ float g_agg[NN * 960];   // segment-sum accumulator, 38.4 MB
__device__ float g_silu_c;

// ---------------- constants -------------------------------------------------
#define INV_SQRT8   0.35355339059327378f
#define INV_SQRT3   0.57735026918962584f
#define INV_SQRT32  0.17677669529663687f
#define CS_CONST    0.38268343236508984f   /* sin(pi/8) */
#define CX_CONST    0.92387953251128674f   /* cos(pi/8) */
#define F0_CONST    0.025515518153991442f  /* 0.25 / sqrt(96) */
#define F1_CONST    0.022097086912079612f  /* 0.25 / sqrt(128) */
#define F2_CONST    0.025515518153991442f  /* 0.25 / sqrt(96) */

// ---------------- SILU normalization constant (deterministic) ---------------
// SILU_C = sqrt( int e^{-x^2/2} dx / int e^{-x^2/2} silu(x)^2 dx )
// Composite Simpson on [-12,12], 8192 intervals, fp64: error << 1e-10.
__global__ void silu_const_kernel() {
    __shared__ double sn[256], sd[256];
    double ln = 0.0, ld = 0.0;
    for (int i = threadIdx.x; i <= 8192; i += 256) {
        double x = -12.0 + (24.0 / 8192.0) * (double)i;
        double c = (i == 0 || i == 8192) ? 1.0 : ((i & 1) ? 4.0 : 2.0);
        double wgt = c * exp(-0.5 * x * x);
        double s = x / (1.0 + exp(-x));
        ln += wgt * s * s;
        ld += wgt;
    }
    sn[threadIdx.x] = ln; sd[threadIdx.x] = ld;
    __syncthreads();
    for (int off = 128; off > 0; off >>= 1) {
        if (threadIdx.x < off) {
            sn[threadIdx.x] += sn[threadIdx.x + off];
            sd[threadIdx.x] += sd[threadIdx.x + off];
        }
        __syncthreads();
    }
    if (threadIdx.x == 0) g_silu_c = (float)sqrt(sd[0] / sn[0]);
}

// ---------------- kernel 1: per-node lin1 -> g_Y ----------------------------
// Y[n][0:64]   = (x0 @ lin1_w0) * a / 8
// Y[n][64+u*3+i] = (sum_t x1[t,i] * lin1_w1[t,u]) * a / sqrt(32)
__global__ __launch_bounds__(256) void node_pre_kernel(
    const float* __restrict__ node_input, const float* __restrict__ node_attr,
    const float* __restrict__ lin1_w0, const float* __restrict__ lin1_w1)
{
    extern __shared__ float sm[];
    float* w0 = sm;            // 4096
    float* w1 = sm + 4096;     // 1024
    float* rows = sm + 5120;   // 8 * 160
    for (int i = threadIdx.x; i < 4096; i += blockDim.x) w0[i] = lin1_w0[i];
    for (int i = threadIdx.x; i < 1024; i += blockDim.x) w1[i] = lin1_w1[i];
    __syncthreads();
    const int warp = threadIdx.x >> 5, lane = threadIdx.x & 31;
    const int nw = (gridDim.x * blockDim.x) >> 5;
    const int gw = (blockIdx.x * blockDim.x + threadIdx.x) >> 5;
    float* row = rows + warp * 160;
    for (int n = gw; n < NN; n += nw) {
#pragma unroll
        for (int t = 0; t < 5; t++)
            row[lane + 32 * t] = node_input[n * 160 + lane + 32 * t];
        __syncwarp();
        float a = node_attr[n];
        float sc0 = a * 0.125f;
        float sc1 = a * INV_SQRT32;
        float outv[5];
#pragma unroll
        for (int t = 0; t < 5; t++) {
            int c = lane + 32 * t;
            float acc = 0.f;
            if (c < 64) {
                for (int i = 0; i < 64; i++) acc += row[i] * w0[i * 64 + c];
                acc *= sc0;
            } else {
                int cc = c - 64;
                int v = cc / 3, i = cc - 3 * v;
                for (int u = 0; u < 32; u++) acc += row[64 + u * 3 + i] * w1[u * 32 + v];
                acc *= sc1;
            }
            outv[t] = acc;
        }
        __syncwarp();
#pragma unroll
        for (int t = 0; t < 5; t++)
            g_Y[n * 160 + lane + 32 * t] = outv[t];
    }
}

// ---------------- kernel 2: per-edge FC + tensor-product + scatter ----------
// Warp handles EPW=4 edges per pass. Lane owns w-channels m = lane + 32t.
// agg layout per node (960): k0@0(64) k1@64(32) k2@96(64x3) k3@288(32x3)
//                            k4@384(32x3) k5@480(64x5) k6@800(32x5)
__global__ __launch_bounds__(256) void edge_kernel(
    const int* __restrict__ edge_src, const int* __restrict__ edge_dst,
    const float* __restrict__ edge_attr, const float* __restrict__ ele,
    const float* __restrict__ fc_w0, const float* __restrict__ fc_w1)
{
    extern __shared__ float sm[];
    float* w0 = sm;                    // 512
    float* w1 = sm + 512;              // 20480
    float* hall = sm + 20992;          // 8 * EPW * 64
    float* yall = hall + 8 * EPW * 64; // 8 * EPW * 160
    for (int i = threadIdx.x; i < 512; i += blockDim.x) w0[i] = fc_w0[i];
    for (int i = threadIdx.x; i < 64 * 320; i += blockDim.x) w1[i] = fc_w1[i];
    __syncthreads();
    const float silu_c = g_silu_c;
    const int warp = threadIdx.x >> 5, lane = threadIdx.x & 31;
    const int nw = (gridDim.x * blockDim.x) >> 5;
    const int gw = (blockIdx.x * blockDim.x + threadIdx.x) >> 5;
    float* h = hall + warp * (EPW * 64);
    float* y = yall + warp * (EPW * 160);

    for (int base = gw * EPW; base < NE; base += nw * EPW) {
        int dsts[EPW];
        float EA0[EPW], EA1[EPW][3], EA2[EPW][5];
#pragma unroll
        for (int q = 0; q < EPW; q++) {
            int e = base + q;                      // NE % EPW == 0
            int src = edge_src[e];
            dsts[q] = edge_dst[e];
            float el = (lane < 8) ? ele[e * 8 + lane] : 0.f;
            float a0 = 0.f, a1 = 0.f;
#pragma unroll
            for (int i = 0; i < 8; i++) {
                float ei = __shfl_sync(0xffffffffu, el, i);
                a0 += ei * w0[i * 64 + lane];
                a1 += ei * w0[i * 64 + 32 + lane];
            }
            a0 *= INV_SQRT8; a1 *= INV_SQRT8;
            h[q * 64 + lane]      = silu_c * a0 / (1.f + __expf(-a0));
            h[q * 64 + 32 + lane] = silu_c * a1 / (1.f + __expf(-a1));
#pragma unroll
            for (int t = 0; t < 5; t++)
                y[q * 160 + lane + 32 * t] = g_Y[src * 160 + lane + 32 * t];
            float ea = (lane < 9) ? edge_attr[e * 9 + lane] : 0.f;
            EA0[q] = __shfl_sync(0xffffffffu, ea, 0);
#pragma unroll
            for (int k = 0; k < 3; k++) EA1[q][k] = __shfl_sync(0xffffffffu, ea, 1 + k);
#pragma unroll
            for (int k = 0; k < 5; k++) EA2[q][k] = __shfl_sync(0xffffffffu, ea, 4 + k);
        }
        __syncwarp();

        // w[e, lane + 32t] = (1/8) * sum_j h[j] * fc_w1[j,·]
        float wv[EPW][10];
#pragma unroll
        for (int q = 0; q < EPW; q++)
#pragma unroll
            for (int t = 0; t < 10; t++) wv[q][t] = 0.f;
        for (int j = 0; j < 64; j++) {
            float h0 = h[j], h1 = h[64 + j], h2 = h[128 + j], h3 = h[192 + j];
            const float* wr = w1 + j * 320 + lane;
#pragma unroll
            for (int t = 0; t < 10; t++) {
                float wt = wr[32 * t];
                wv[0][t] += h0 * wt;
                wv[1][t] += h1 * wt;
                wv[2][t] += h2 * wt;
                wv[3][t] += h3 * wt;
            }
        }
#pragma unroll
        for (int q = 0; q < EPW; q++)
#pragma unroll
            for (int t = 0; t < 10; t++) wv[q][t] *= 0.125f;

#pragma unroll
        for (int q = 0; q < EPW; q++) {
            float* aggrow = g_agg + (long long)dsts[q] * 960;
            const float* yq = y + q * 160;
            float e0 = EA0[q];
            float y0a = yq[lane], y0b = yq[32 + lane];
            // k0 (l=0 x l=0 -> l=0)
            atomicAdd(aggrow + lane,      y0a * e0 * wv[q][0]);
            atomicAdd(aggrow + 32 + lane, y0b * e0 * wv[q][1]);
            // k2 (l=0 x l=1 -> l=1), k5 (l=0 x l=2 -> l=2); sqrt(2l+1)*C = identity
#pragma unroll
            for (int k = 0; k < 3; k++) {
                atomicAdd(aggrow + 96 + lane * 3 + k,        y0a * EA1[q][k] * wv[q][2]);
                atomicAdd(aggrow + 96 + (lane + 32) * 3 + k, y0b * EA1[q][k] * wv[q][3]);
            }
#pragma unroll
            for (int k = 0; k < 5; k++) {
                atomicAdd(aggrow + 480 + lane * 5 + k,        y0a * EA2[q][k] * wv[q][4]);
                atomicAdd(aggrow + 480 + (lane + 32) * 5 + k, y0b * EA2[q][k] * wv[q][5]);
            }
            float ya = yq[64 + lane * 3], yb = yq[64 + lane * 3 + 1], yc = yq[64 + lane * 3 + 2];
            // k3 (l=1 x l=0 -> l=1)
            float w3 = wv[q][6] * e0;
            atomicAdd(aggrow + 288 + lane * 3 + 0, ya * w3);
            atomicAdd(aggrow + 288 + lane * 3 + 1, yb * w3);
            atomicAdd(aggrow + 288 + lane * 3 + 2, yc * w3);
            // k1 (l=1 x l=1 -> l=0): dot / sqrt(3)
            atomicAdd(aggrow + 64 + lane,
                INV_SQRT3 * (ya * EA1[q][0] + yb * EA1[q][1] + yc * EA1[q][2]) * wv[q][7]);
            // k6 (l=1 x l=1 -> l=2): sqrt(5)*W112 folded
            {
                float w6 = wv[q][8];
                const float C2 = 0.70710678118654757f;  // 1/sqrt(2)
                const float C6 = 0.40824829046386302f;  // 1/sqrt(6)
                float b0 = EA1[q][0], b1 = EA1[q][1], b2 = EA1[q][2];
                atomicAdd(aggrow + 800 + lane * 5 + 0, -C2 * (ya * b2 + yc * b0) * w6);
                atomicAdd(aggrow + 800 + lane * 5 + 1, -C2 * (ya * b1 + yb * b0) * w6);
                atomicAdd(aggrow + 800 + lane * 5 + 2,  C6 * (ya * b0 - 2.f * yb * b1 + yc * b2) * w6);
                atomicAdd(aggrow + 800 + lane * 5 + 3, -C2 * (yb * b2 + yc * b1) * w6);
                atomicAdd(aggrow + 800 + lane * 5 + 4,  C2 * (ya * b0 - yc * b2) * w6);
            }
            // k4 (l=1 x l=2 -> l=1): sqrt(3)*W121 folded
            {
                float w4 = wv[q][9];
                const float A = 0.54772255750516607f;   // sqrt(3/10)
                const float B = 0.31622776601683794f;   // 1/sqrt(10)
                float c0 = EA2[q][0], c1 = EA2[q][1], c2 = EA2[q][2], c3 = EA2[q][3], c4 = EA2[q][4];
                atomicAdd(aggrow + 384 + lane * 3 + 0, (A * (yb * c1 + yc * c0) - ya * (B * c2 + A * c4)) * w4);
                atomicAdd(aggrow + 384 + lane * 3 + 1, (A * (ya * c1 + yc * c3) + 2.f * B * yb * c2) * w4);
                atomicAdd(aggrow + 384 + lane * 3 + 2, (A * (ya * c0 + yb * c3 + yc * c4) - B * yc * c2) * w4);
            }
        }
        __syncwarp();
    }
}

// ---------------- kernel 3: per-node lin2 + skip + output -------------------
__global__ __launch_bounds__(256) void node_post_kernel(
    const float* __restrict__ node_input, const float* __restrict__ node_attr,
    const float* __restrict__ sc_w0, const float* __restrict__ sc_w1,
    const float* __restrict__ l2w0, const float* __restrict__ l2w1,
    const float* __restrict__ l2w2, float* __restrict__ out)
{
    extern __shared__ float sm[];
    float* Wsc0 = sm;             // 4096
    float* Wsc1 = sm + 4096;      // 1024
    float* W0 = sm + 5120;        // 6144
    float* W1 = sm + 11264;       // 4096
    float* W2 = sm + 15360;       // 3072
    float* stage = sm + 18432;    // 8 * 1120
    for (int i = threadIdx.x; i < 4096; i += blockDim.x) Wsc0[i] = sc_w0[i];
    for (int i = threadIdx.x; i < 1024; i += blockDim.x) Wsc1[i] = sc_w1[i];
    for (int i = threadIdx.x; i < 6144; i += blockDim.x) W0[i] = l2w0[i];
    for (int i = threadIdx.x; i < 4096; i += blockDim.x) W1[i] = l2w1[i];
    for (int i = threadIdx.x; i < 3072; i += blockDim.x) W2[i] = l2w2[i];
    __syncthreads();
    const int warp = threadIdx.x >> 5, lane = threadIdx.x & 31;
    const int nw = (gridDim.x * blockDim.x) >> 5;
    const int gw = (blockIdx.x * blockDim.x + threadIdx.x) >> 5;
    float* ag = stage + warp * 1120;
    float* row = ag + 960;
    for (int n = gw; n < NN; n += nw) {
        for (int j = lane; j < 960; j += 32) ag[j] = g_agg[(long long)n * 960 + j];
#pragma unroll
        for (int t = 0; t < 5; t++) row[lane + 32 * t] = node_input[n * 160 + lane + 32 * t];
        __syncwarp();
        float a = node_attr[n];
        float f0 = a * F0_CONST, f1 = a * F1_CONST, f2 = a * F2_CONST;
        float g0 = a * 0.125f, g1 = a * INV_SQRT32;
        float res[10];
#pragma unroll
        for (int t = 0; t < 2; t++) {
            int c = lane + 32 * t;
            float o = 0.f, s = 0.f;
            for (int u = 0; u < 96; u++) o += ag[u] * W0[u * 64 + c];
            for (int i = 0; i < 64; i++) s += row[i] * Wsc0[i * 64 + c];
            res[t] = CX_CONST * (o * f0) + CS_CONST * (s * g0);
        }
#pragma unroll
        for (int t = 2; t < 5; t++) {
            int cc = lane + 32 * t - 64;
            int v = cc / 3, i = cc - v * 3;
            float o = 0.f, s = 0.f;
            for (int u = 0; u < 128; u++) o += ag[96 + u * 3 + i] * W1[u * 32 + v];
            for (int u = 0; u < 32; u++) s += row[64 + u * 3 + i] * Wsc1[u * 32 + v];
            res[t] = CX_CONST * (o * f1) + CS_CONST * (s * g1);
        }
#pragma unroll
        for (int t = 5; t < 10; t++) {
            int cc = lane + 32 * t - 160;
            int v = cc / 5, k = cc - v * 5;
            float o = 0.f;
            for (int u = 0; u < 96; u++) o += ag[480 + u * 5 + k] * W2[u * 32 + v];
            res[t] = o * f2;
        }
        __syncwarp();
#pragma unroll
        for (int t = 0; t < 10; t++)
            out[(long long)n * 320 + lane + 32 * t] = res[t];
    }
}

// ---------------- launch ----------------------------------------------------
extern "C" void kernel_launch(void* const* d_in, const int* in_sizes, int n_in,
                              void* d_out, int out_size) {
    (void)in_sizes; (void)n_in; (void)out_size;
    const float* node_input = (const float*)d_in[0];
    const float* node_attr  = (const float*)d_in[1];
    const int*   edge_src   = (const int*)d_in[2];
    const int*   edge_dst   = (const int*)d_in[3];
    const float* edge_attr  = (const float*)d_in[4];
    const float* ele        = (const float*)d_in[5];
    const float* sc_w0      = (const float*)d_in[6];
    const float* sc_w1      = (const float*)d_in[7];
    const float* lin1_w0    = (const float*)d_in[8];
    const float* lin1_w1    = (const float*)d_in[9];
    const float* fc_w0      = (const float*)d_in[10];
    const float* fc_w1      = (const float*)d_in[11];
    const float* lin2_w0    = (const float*)d_in[12];
    const float* lin2_w1    = (const float*)d_in[13];
    const float* lin2_w2    = (const float*)d_in[14];
    float* out = (float*)d_out;

    const int PRE_SMEM  = (4096 + 1024 + 8 * 160) * 4;
    const int EDGE_SMEM = (512 + 20480 + 8 * EPW * 64 + 8 * EPW * 160) * 4;
    const int POST_SMEM = (4096 + 1024 + 6144 + 4096 + 3072 + 8 * 1120) * 4;

    cudaFuncSetAttribute(node_pre_kernel, cudaFuncAttributeMaxDynamicSharedMemorySize, PRE_SMEM);
    cudaFuncSetAttribute(edge_kernel, cudaFuncAttributeMaxDynamicSharedMemorySize, EDGE_SMEM);
    cudaFuncSetAttribute(node_post_kernel, cudaFuncAttributeMaxDynamicSharedMemorySize, POST_SMEM);

    void* aggp = 0;
    cudaGetSymbolAddress(&aggp, g_agg);
    cudaMemsetAsync(aggp, 0, sizeof(float) * (size_t)NN * 960);

    silu_const_kernel<<<1, 256>>>();
    node_pre_kernel<<<304, 256, PRE_SMEM>>>(node_input, node_attr, lin1_w0, lin1_w1);
    edge_kernel<<<304, 256, EDGE_SMEM>>>(edge_src, edge_dst, edge_attr, ele, fc_w0, fc_w1);
    node_post_kernel<<<304, 256, POST_SMEM>>>(node_input, node_attr, sc_w0, sc_w1,
                                              lin2_w0, lin2_w1, lin2_w2, out);
}

// round 17
// speedup vs baseline: 1.2046x; 1.2046x over previous
#include <cuda_runtime.h>
#include <math.h>

#define NN 10000
#define NE 160000

// ---------------- scratch (static device globals; no allocation) ------------
__device__ float  g_Y[NN * 160];        // lin1 output per node
__device__ int    g_cnt[NN];            // degree histogram
__device__ int    g_cur[NN];            // scatter cursors
__device__ int    g_off[NN + 1];        // CSR row offsets
__device__ int    g_csr[NE];            // CSR edge ids (by dst)
__device__ int    g_tick;               // work-steal ticket
__device__ float  g_silu_c;
// prepped weights
__device__ float2 g_pw1[64 * 5 * 32];   // fc_w1 paired (t, t+1) per lane
__device__ float  g_W0t[64 * 100];      // lin2_w0 transposed [c][u], pad 100
__device__ float  g_W1t[32 * 132];      // lin2_w1 transposed [v][u], pad 132
__device__ float  g_W2t[32 * 100];      // lin2_w2 transposed [v][u], pad 100
__device__ float  g_S0t[64 * 68];       // sc_w0 transposed [c][i], pad 68
__device__ float  g_S1t[32 * 36];       // sc_w1 transposed [v][u], pad 36

// ---------------- constants -------------------------------------------------
#define INV_SQRT8   0.35355339059327378f
#define INV_SQRT3   0.57735026918962584f
#define INV_SQRT32  0.17677669529663687f
#define CS_CONST    0.38268343236508984f   /* sin(pi/8) */
#define CX_CONST    0.92387953251128674f   /* cos(pi/8) */
#define F0_CONST    0.025515518153991442f  /* 0.25 / sqrt(96) */
#define F1_CONST    0.022097086912079612f  /* 0.25 / sqrt(128) */
#define F2_CONST    0.025515518153991442f  /* 0.25 / sqrt(96) */

// ---------------- f32x2 helpers (Blackwell packed fp32) ---------------------
__device__ __forceinline__ unsigned long long f2pack(float lo, float hi) {
    unsigned long long r;
    asm("mov.b64 %0, {%1, %2};" : "=l"(r) : "f"(lo), "f"(hi));
    return r;
}
__device__ __forceinline__ void f2unpack(unsigned long long v, float& lo, float& hi) {
    asm("mov.b64 {%0, %1}, %2;" : "=f"(lo), "=f"(hi) : "l"(v));
}
__device__ __forceinline__ unsigned long long f2fma(unsigned long long a,
                                                    unsigned long long b,
                                                    unsigned long long c) {
    unsigned long long d;
    asm("fma.rn.f32x2 %0, %1, %2, %3;" : "=l"(d) : "l"(a), "l"(b), "l"(c));
    return d;
}

// ---------------- SILU normalization constant (deterministic) ---------------
__global__ void silu_const_kernel() {
    __shared__ double sn[256], sd[256];
    double ln = 0.0, ld = 0.0;
    for (int i = threadIdx.x; i <= 8192; i += 256) {
        double x = -12.0 + (24.0 / 8192.0) * (double)i;
        double c = (i == 0 || i == 8192) ? 1.0 : ((i & 1) ? 4.0 : 2.0);
        double wgt = c * exp(-0.5 * x * x);
        double s = x / (1.0 + exp(-x));
        ln += wgt * s * s;
        ld += wgt;
    }
    sn[threadIdx.x] = ln; sd[threadIdx.x] = ld;
    __syncthreads();
    for (int off = 128; off > 0; off >>= 1) {
        if (threadIdx.x < off) {
            sn[threadIdx.x] += sn[threadIdx.x + off];
            sd[threadIdx.x] += sd[threadIdx.x + off];
        }
        __syncthreads();
    }
    if (threadIdx.x == 0) g_silu_c = (float)sqrt(sd[0] / sn[0]);
}

// ---------------- weight prep: transpose/pad/pack ---------------------------
__global__ void prep_weights_kernel(
    const float* __restrict__ fc_w1,
    const float* __restrict__ l2w0, const float* __restrict__ l2w1,
    const float* __restrict__ l2w2,
    const float* __restrict__ sc_w0, const float* __restrict__ sc_w1)
{
    int i = blockIdx.x * blockDim.x + threadIdx.x;
    if (i < 64 * 5 * 32) {            // packed fc_w1
        int lane = i & 31, tp = (i >> 5) % 5, j = i / 160;
        g_pw1[i] = make_float2(fc_w1[j * 320 + lane + 64 * tp],
                               fc_w1[j * 320 + lane + 64 * tp + 32]);
    }
    if (i < 64 * 96) { int c = i / 96, u = i % 96; g_W0t[c * 100 + u] = l2w0[u * 64 + c]; }
    if (i < 32 * 128){ int v = i / 128, u = i % 128; g_W1t[v * 132 + u] = l2w1[u * 32 + v]; }
    if (i < 32 * 96) { int v = i / 96, u = i % 96; g_W2t[v * 100 + u] = l2w2[u * 32 + v]; }
    if (i < 64 * 64) { int c = i / 64, u = i % 64; g_S0t[c * 68 + u] = sc_w0[u * 64 + c]; }
    if (i < 32 * 32) { int v = i / 32, u = i % 32; g_S1t[v * 36 + u] = sc_w1[u * 32 + v]; }
}

// ---------------- CSR build -------------------------------------------------
__global__ void hist_kernel(const int* __restrict__ dst) {
    int e = blockIdx.x * blockDim.x + threadIdx.x;
    if (e < NE) atomicAdd(&g_cnt[dst[e]], 1);
}
__global__ void scan_kernel() {
    __shared__ int sh[1024];
    __shared__ int carry_s;
    if (threadIdx.x == 0) { carry_s = 0; g_off[0] = 0; }
    __syncthreads();
    for (int base = 0; base < NN; base += 1024) {
        int i = base + threadIdx.x;
        int v = (i < NN) ? g_cnt[i] : 0;
        sh[threadIdx.x] = v;
        __syncthreads();
        for (int o = 1; o < 1024; o <<= 1) {
            int t = (threadIdx.x >= o) ? sh[threadIdx.x - o] : 0;
            __syncthreads();
            sh[threadIdx.x] += t;
            __syncthreads();
        }
        if (i < NN) g_off[i + 1] = carry_s + sh[threadIdx.x];
        __syncthreads();
        if (threadIdx.x == 0) carry_s += sh[1023];
        __syncthreads();
    }
}
__global__ void scatter_kernel(const int* __restrict__ dst) {
    int e = blockIdx.x * blockDim.x + threadIdx.x;
    if (e < NE) {
        int d = dst[e];
        int p = atomicAdd(&g_cur[d], 1);
        g_csr[g_off[d] + p] = e;
    }
}

// ---------------- kernel 1: per-node lin1 -> g_Y (verified in R2) -----------
__global__ __launch_bounds__(256) void node_pre_kernel(
    const float* __restrict__ node_input, const float* __restrict__ node_attr,
    const float* __restrict__ lin1_w0, const float* __restrict__ lin1_w1)
{
    extern __shared__ float sm[];
    float* w0 = sm;            // 4096
    float* w1 = sm + 4096;     // 1024
    float* rows = sm + 5120;   // 8 * 160
    for (int i = threadIdx.x; i < 4096; i += blockDim.x) w0[i] = lin1_w0[i];
    for (int i = threadIdx.x; i < 1024; i += blockDim.x) w1[i] = lin1_w1[i];
    __syncthreads();
    const int warp = threadIdx.x >> 5, lane = threadIdx.x & 31;
    const int nw = (gridDim.x * blockDim.x) >> 5;
    const int gw = (blockIdx.x * blockDim.x + threadIdx.x) >> 5;
    float* row = rows + warp * 160;
    for (int n = gw; n < NN; n += nw) {
#pragma unroll
        for (int t = 0; t < 5; t++)
            row[lane + 32 * t] = node_input[n * 160 + lane + 32 * t];
        __syncwarp();
        float a = node_attr[n];
        float sc0 = a * 0.125f;
        float sc1 = a * INV_SQRT32;
        float outv[5];
#pragma unroll
        for (int t = 0; t < 5; t++) {
            int c = lane + 32 * t;
            float acc = 0.f;
            if (c < 64) {
                for (int i = 0; i < 64; i++) acc += row[i] * w0[i * 64 + c];
                acc *= sc0;
            } else {
                int cc = c - 64;
                int v = cc / 3, i = cc - 3 * v;
                for (int u = 0; u < 32; u++) acc += row[64 + u * 3 + i] * w1[u * 32 + v];
                acc *= sc1;
            }
            outv[t] = acc;
        }
        __syncwarp();
#pragma unroll
        for (int t = 0; t < 5; t++)
            g_Y[n * 160 + lane + 32 * t] = outv[t];
    }
}

// ---------------- fused gather + tensor product + lin2 ----------------------
// One warp per node (work-stealing). acc register layout per lane (30):
//  0: k0a  1: k0b  2-4: k2a  5-7: k2b  8-12: k5a  13-17: k5b
//  18-20: k3  21: k1  22-26: k6  27-29: k4
// smem staging layout per warp (ag, 960):
//  [0..95]   m0: k0a@lane, k0b@32+lane, k1@64+lane
//  [96..479] m1 transposed [i][128]: u<64 k2 (a@lane, b@32+lane), 64..95 k3, 96..127 k4
//  [480..959] m2 transposed [k][96]: u<64 k5 (a@lane, b@32+lane), 64..95 k6
__global__ __launch_bounds__(384, 1) void fused_kernel(
    const float* __restrict__ node_input, const float* __restrict__ node_attr,
    const int* __restrict__ edge_src,
    const float* __restrict__ edge_attr, const float* __restrict__ ele,
    const float* __restrict__ fc_w0, float* __restrict__ out)
{
    extern __shared__ float sm[];
    float* s_w0   = sm;                 // 512
    float* s_pw1f = sm + 512;           // 20480 (float2[10240])
    float* s_W0t  = sm + 20992;         // 6400
    float* s_W1t  = sm + 27392;         // 4224
    float* s_W2t  = sm + 31616;         // 3200
    float* s_S0t  = sm + 34816;         // 4352
    float* s_S1t  = sm + 39168;         // 1152
    float* s_stage= sm + 40320;         // 12 * 1216

    for (int i = threadIdx.x; i < 512;   i += blockDim.x) s_w0[i]  = fc_w0[i];
    {
        const float* pw = (const float*)g_pw1;
        for (int i = threadIdx.x; i < 20480; i += blockDim.x) s_pw1f[i] = pw[i];
    }
    for (int i = threadIdx.x; i < 6400; i += blockDim.x) s_W0t[i] = g_W0t[i];
    for (int i = threadIdx.x; i < 4224; i += blockDim.x) s_W1t[i] = g_W1t[i];
    for (int i = threadIdx.x; i < 3200; i += blockDim.x) s_W2t[i] = g_W2t[i];
    for (int i = threadIdx.x; i < 4352; i += blockDim.x) s_S0t[i] = g_S0t[i];
    for (int i = threadIdx.x; i < 1152; i += blockDim.x) s_S1t[i] = g_S1t[i];
    __syncthreads();

    const float silu_c = g_silu_c;
    const int warp = threadIdx.x >> 5, lane = threadIdx.x & 31;
    float* hbuf = s_stage + warp * 1216;   // 256 floats (h in edge phase, row in post)
    float* ag   = hbuf + 256;              // 960 floats
    const unsigned long long* s_pw1 = (const unsigned long long*)s_pw1f;

    for (;;) {
        int n;
        if (lane == 0) n = atomicAdd(&g_tick, 1);
        n = __shfl_sync(0xffffffffu, n, 0);
        if (n >= NN) break;

        const int off0 = g_off[n], off1 = g_off[n + 1];
        float acc[30];
#pragma unroll
        for (int i = 0; i < 30; i++) acc[i] = 0.f;

        for (int base = off0; base < off1; base += 4) {
            const int nb = min(4, off1 - base);
            float y0a[4], y0b[4], ya[4], yb[4], yc[4];
            float EA0[4], EA1[4][3], EA2[4][5];
#pragma unroll
            for (int q = 0; q < 4; q++) {
                if (q < nb) {
                    int e = g_csr[base + q];
                    int src = edge_src[e];
                    const float* Yr = g_Y + src * 160;
                    y0a[q] = Yr[lane];
                    y0b[q] = Yr[32 + lane];
                    ya[q]  = Yr[64 + lane * 3];
                    yb[q]  = Yr[65 + lane * 3];
                    yc[q]  = Yr[66 + lane * 3];
                    float el = (lane < 8) ? ele[e * 8 + lane] : 0.f;
                    float a0 = 0.f, a1 = 0.f;
#pragma unroll
                    for (int i = 0; i < 8; i++) {
                        float ei = __shfl_sync(0xffffffffu, el, i);
                        a0 += ei * s_w0[i * 64 + lane];
                        a1 += ei * s_w0[i * 64 + 32 + lane];
                    }
                    a0 *= INV_SQRT8; a1 *= INV_SQRT8;
                    hbuf[q * 64 + lane]      = silu_c * a0 / (1.f + __expf(-a0));
                    hbuf[q * 64 + 32 + lane] = silu_c * a1 / (1.f + __expf(-a1));
                    float ea = (lane < 9) ? edge_attr[e * 9 + lane] : 0.f;
                    EA0[q] = __shfl_sync(0xffffffffu, ea, 0);
#pragma unroll
                    for (int k = 0; k < 3; k++) EA1[q][k] = __shfl_sync(0xffffffffu, ea, 1 + k);
#pragma unroll
                    for (int k = 0; k < 5; k++) EA2[q][k] = __shfl_sync(0xffffffffu, ea, 4 + k);
                } else {
                    hbuf[q * 64 + lane] = 0.f;
                    hbuf[q * 64 + 32 + lane] = 0.f;
                }
            }
            __syncwarp();

            // packed FC GEMM: wvp[q][tp] accumulates channels (lane+64tp, lane+64tp+32)
            unsigned long long wvp[4][5];
#pragma unroll
            for (int q = 0; q < 4; q++)
#pragma unroll
                for (int tp = 0; tp < 5; tp++) wvp[q][tp] = 0ull;
#pragma unroll 2
            for (int j = 0; j < 64; j++) {
                unsigned long long hq[4];
#pragma unroll
                for (int q = 0; q < 4; q++) {
                    float hv = hbuf[q * 64 + j];
                    hq[q] = f2pack(hv, hv);
                }
                const unsigned long long* pw = s_pw1 + j * 160 + lane;
#pragma unroll
                for (int tp = 0; tp < 5; tp++) {
                    unsigned long long w2 = pw[tp * 32];
                    wvp[0][tp] = f2fma(hq[0], w2, wvp[0][tp]);
                    wvp[1][tp] = f2fma(hq[1], w2, wvp[1][tp]);
                    wvp[2][tp] = f2fma(hq[2], w2, wvp[2][tp]);
                    wvp[3][tp] = f2fma(hq[3], w2, wvp[3][tp]);
                }
            }
            __syncwarp();

#pragma unroll
            for (int q = 0; q < 4; q++) {
                if (q >= nb) break;
                float wv[10];
#pragma unroll
                for (int tp = 0; tp < 5; tp++) f2unpack(wvp[q][tp], wv[2 * tp], wv[2 * tp + 1]);
#pragma unroll
                for (int t = 0; t < 10; t++) wv[t] *= 0.125f;

                float e0 = EA0[q];
                // k0
                acc[0] += y0a[q] * e0 * wv[0];
                acc[1] += y0b[q] * e0 * wv[1];
                // k2, k5
#pragma unroll
                for (int k = 0; k < 3; k++) {
                    acc[2 + k] += y0a[q] * EA1[q][k] * wv[2];
                    acc[5 + k] += y0b[q] * EA1[q][k] * wv[3];
                }
#pragma unroll
                for (int k = 0; k < 5; k++) {
                    acc[8 + k]  += y0a[q] * EA2[q][k] * wv[4];
                    acc[13 + k] += y0b[q] * EA2[q][k] * wv[5];
                }
                // k3
                float w3 = wv[6] * e0;
                acc[18] += ya[q] * w3;
                acc[19] += yb[q] * w3;
                acc[20] += yc[q] * w3;
                // k1
                acc[21] += INV_SQRT3 * (ya[q] * EA1[q][0] + yb[q] * EA1[q][1] + yc[q] * EA1[q][2]) * wv[7];
                // k6
                {
                    float w6 = wv[8];
                    const float C2 = 0.70710678118654757f;
                    const float C6 = 0.40824829046386302f;
                    float b0 = EA1[q][0], b1 = EA1[q][1], b2 = EA1[q][2];
                    acc[22] += -C2 * (ya[q] * b2 + yc[q] * b0) * w6;
                    acc[23] += -C2 * (ya[q] * b1 + yb[q] * b0) * w6;
                    acc[24] +=  C6 * (ya[q] * b0 - 2.f * yb[q] * b1 + yc[q] * b2) * w6;
                    acc[25] += -C2 * (yb[q] * b2 + yc[q] * b1) * w6;
                    acc[26] +=  C2 * (ya[q] * b0 - yc[q] * b2) * w6;
                }
                // k4
                {
                    float w4 = wv[9];
                    const float A = 0.54772255750516607f;
                    const float B = 0.31622776601683794f;
                    float c0 = EA2[q][0], c1 = EA2[q][1], c2 = EA2[q][2], c3 = EA2[q][3], c4 = EA2[q][4];
                    acc[27] += (A * (yb[q] * c1 + yc[q] * c0) - ya[q] * (B * c2 + A * c4)) * w4;
                    acc[28] += (A * (ya[q] * c1 + yc[q] * c3) + 2.f * B * yb[q] * c2) * w4;
                    acc[29] += (A * (ya[q] * c0 + yb[q] * c3 + yc[q] * c4) - B * yc[q] * c2) * w4;
                }
            }
        }

        // ---- post phase: stage acc -> smem ag (transposed layouts) ----
        ag[lane]      = acc[0];
        ag[32 + lane] = acc[1];
        ag[64 + lane] = acc[21];
#pragma unroll
        for (int k = 0; k < 3; k++) {
            ag[96 + k * 128 + lane]      = acc[2 + k];   // k2a
            ag[96 + k * 128 + 32 + lane] = acc[5 + k];   // k2b
            ag[96 + k * 128 + 64 + lane] = acc[18 + k];  // k3
            ag[96 + k * 128 + 96 + lane] = acc[27 + k];  // k4
        }
#pragma unroll
        for (int k = 0; k < 5; k++) {
            ag[480 + k * 96 + lane]      = acc[8 + k];   // k5a
            ag[480 + k * 96 + 32 + lane] = acc[13 + k];  // k5b
            ag[480 + k * 96 + 64 + lane] = acc[22 + k];  // k6
        }
        // node row into hbuf
#pragma unroll
        for (int t = 0; t < 5; t++)
            hbuf[lane + 32 * t] = node_input[n * 160 + lane + 32 * t];
        __syncwarp();

        const float a = node_attr[n];
        const float f0 = a * F0_CONST, f1 = a * F1_CONST, f2 = a * F2_CONST;
        const float g0 = a * 0.125f,  g1 = a * INV_SQRT32;
        float res[10];

        // t = 0,1: scalar channels (c = lane, lane+32)
        {
            const float4* agv = (const float4*)ag;
            const float4* wA  = (const float4*)(s_W0t + lane * 100);
            const float4* wB  = (const float4*)(s_W0t + (lane + 32) * 100);
            float oA = 0.f, oB = 0.f;
#pragma unroll
            for (int u = 0; u < 24; u++) {
                float4 a4 = agv[u], wa = wA[u], wb = wB[u];
                oA += a4.x * wa.x + a4.y * wa.y + a4.z * wa.z + a4.w * wa.w;
                oB += a4.x * wb.x + a4.y * wb.y + a4.z * wb.z + a4.w * wb.w;
            }
            const float4* rv = (const float4*)hbuf;
            const float4* sA = (const float4*)(s_S0t + lane * 68);
            const float4* sB = (const float4*)(s_S0t + (lane + 32) * 68);
            float pA = 0.f, pB = 0.f;
#pragma unroll
            for (int u = 0; u < 16; u++) {
                float4 r4 = rv[u], wa = sA[u], wb = sB[u];
                pA += r4.x * wa.x + r4.y * wa.y + r4.z * wa.z + r4.w * wa.w;
                pB += r4.x * wb.x + r4.y * wb.y + r4.z * wb.z + r4.w * wb.w;
            }
            res[0] = CX_CONST * (oA * f0) + CS_CONST * (pA * g0);
            res[1] = CX_CONST * (oB * f0) + CS_CONST * (pB * g0);
        }
        // t = 2..4: l=1 channels
#pragma unroll
        for (int t = 2; t < 5; t++) {
            int cc = lane + 32 * t - 64;
            int v = cc / 3, i = cc - v * 3;
            const float4* av = (const float4*)(ag + 96 + i * 128);
            const float4* wv_ = (const float4*)(s_W1t + v * 132);
            float o = 0.f;
#pragma unroll
            for (int u = 0; u < 32; u++) {
                float4 a4 = av[u], w4 = wv_[u];
                o += a4.x * w4.x + a4.y * w4.y + a4.z * w4.z + a4.w * w4.w;
            }
            float s = 0.f;
            const float* sw = s_S1t + v * 36;
#pragma unroll
            for (int u = 0; u < 32; u++)
                s += hbuf[64 + u * 3 + i] * sw[u];
            res[t] = CX_CONST * (o * f1) + CS_CONST * (s * g1);
        }
        // t = 5..9: l=2 channels
#pragma unroll
        for (int t = 5; t < 10; t++) {
            int cc = lane + 32 * t - 160;
            int v = cc / 5, k = cc - v * 5;
            const float4* av = (const float4*)(ag + 480 + k * 96);
            const float4* wv_ = (const float4*)(s_W2t + v * 100);
            float o = 0.f;
#pragma unroll
            for (int u = 0; u < 24; u++) {
                float4 a4 = av[u], w4 = wv_[u];
                o += a4.x * w4.x + a4.y * w4.y + a4.z * w4.z + a4.w * w4.w;
            }
            res[t] = o * f2;
        }
        __syncwarp();
#pragma unroll
        for (int t = 0; t < 10; t++)
            out[n * 320 + lane + 32 * t] = res[t];
        __syncwarp();
    }
}

// ---------------- launch ----------------------------------------------------
extern "C" void kernel_launch(void* const* d_in, const int* in_sizes, int n_in,
                              void* d_out, int out_size) {
    (void)in_sizes; (void)n_in; (void)out_size;
    const float* node_input = (const float*)d_in[0];
    const float* node_attr  = (const float*)d_in[1];
    const int*   edge_src   = (const int*)d_in[2];
    const int*   edge_dst   = (const int*)d_in[3];
    const float* edge_attr  = (const float*)d_in[4];
    const float* ele        = (const float*)d_in[5];
    const float* sc_w0      = (const float*)d_in[6];
    const float* sc_w1      = (const float*)d_in[7];
    const float* lin1_w0    = (const float*)d_in[8];
    const float* lin1_w1    = (const float*)d_in[9];
    const float* fc_w0      = (const float*)d_in[10];
    const float* fc_w1      = (const float*)d_in[11];
    const float* lin2_w0    = (const float*)d_in[12];
    const float* lin2_w1    = (const float*)d_in[13];
    const float* lin2_w2    = (const float*)d_in[14];
    float* out = (float*)d_out;

    const int PRE_SMEM   = (4096 + 1024 + 8 * 160) * 4;
    const int FUSED_SMEM = (40320 + 12 * 1216) * 4;   // 219648 B

    cudaFuncSetAttribute(node_pre_kernel, cudaFuncAttributeMaxDynamicSharedMemorySize, PRE_SMEM);
    cudaFuncSetAttribute(fused_kernel, cudaFuncAttributeMaxDynamicSharedMemorySize, FUSED_SMEM);

    int dev = 0, sms = 148;
    cudaGetDevice(&dev);
    cudaDeviceGetAttribute(&sms, cudaDevAttrMultiProcessorCount, dev);

    void* p = 0;
    cudaGetSymbolAddress(&p, g_cnt);  cudaMemsetAsync(p, 0, NN * sizeof(int));
    cudaGetSymbolAddress(&p, g_cur);  cudaMemsetAsync(p, 0, NN * sizeof(int));
    cudaGetSymbolAddress(&p, g_tick); cudaMemsetAsync(p, 0, sizeof(int));

    silu_const_kernel<<<1, 256>>>();
    prep_weights_kernel<<<40, 256>>>(fc_w1, lin2_w0, lin2_w1, lin2_w2, sc_w0, sc_w1);
    hist_kernel<<<(NE + 255) / 256, 256>>>(edge_dst);
    scan_kernel<<<1, 1024>>>();
    scatter_kernel<<<(NE + 255) / 256, 256>>>(edge_dst);
    node_pre_kernel<<<304, 256, PRE_SMEM>>>(node_input, node_attr, lin1_w0, lin1_w1);
    fused_kernel<<<sms, 384, FUSED_SMEM>>>(node_input, node_attr, edge_src,
                                           edge_attr, ele, fc_w0, out);
}